// round 1
// baseline (speedup 1.0000x reference)
#include <cuda_runtime.h>

// Problem constants (fixed by the reference setup)
#define B_  32
#define C_  256
#define O_  256
#define NX  961     // 31*31
#define NZ  49      // 7*7

#define TILE 64
#define KT   16
#define KT2  32

// Scratch (device globals; no runtime allocation)
__device__ float g_XT [(size_t)B_ * C_ * NX];          // xf_trans            [B,C,Nx]
__device__ float g_CAT[(size_t)B_ * 3 * C_ * NX];      // [emb|self_emb|xf_g] [B,3C,Nx]
__device__ float g_ZT [(size_t)B_ * C_ * NZ];          // zf_trans            [B,C,Nz]
__device__ float g_ZG [(size_t)B_ * C_ * NZ];          // zf_g                [B,C,Nz]
__device__ float g_PS [(size_t)B_ * NX * NX];          // self attn probs     [B,Nx,Nx]
__device__ float g_PZ [(size_t)B_ * NX * NZ];          // cross attn probs    [B,Nx,Nz]

// ---------------------------------------------------------------------------
// conv1x1 as GEMM: Y[b,o,n] = act( scale[o]*(sum_k W[o,k]*X[b,k,n]) + shift[o] )
// gamma==nullptr -> Y = gemm + bias (no relu). Else BN fold + relu.
// O must be a multiple of 64, K a multiple of 16 (true for all uses: 256/768).
// ---------------------------------------------------------------------------
__global__ void conv_gemm(const float* __restrict__ W, const float* __restrict__ X,
                          float* __restrict__ Y,
                          const float* __restrict__ bias,
                          const float* __restrict__ gamma, const float* __restrict__ beta,
                          const float* __restrict__ mean,  const float* __restrict__ var,
                          int Kdim, int Ndim,
                          long x_bstride, long y_bstride, long y_off)
{
    const int b = blockIdx.z;
    const float* Xb = X + (long)b * x_bstride;
    float* Yb = Y + (long)b * y_bstride + y_off;

    __shared__ float Ws[KT][TILE];
    __shared__ float Xs[KT][TILE];

    const int t  = threadIdx.x;
    const int tx = t & 15;
    const int ty = t >> 4;
    const int n0 = blockIdx.x * TILE;
    const int o0 = blockIdx.y * TILE;

    float acc[4][4] = {};

    for (int k0 = 0; k0 < Kdim; k0 += KT) {
#pragma unroll
        for (int r = 0; r < 4; r++) {
            int idx = t + r * 256;
            int kk = idx % KT;
            int oo = idx / KT;
            Ws[kk][oo] = W[(long)(o0 + oo) * Kdim + k0 + kk];
        }
#pragma unroll
        for (int r = 0; r < 4; r++) {
            int idx = t + r * 256;
            int nn = idx % TILE;
            int kk = idx / TILE;
            int n = n0 + nn;
            Xs[kk][nn] = (n < Ndim) ? Xb[(long)(k0 + kk) * Ndim + n] : 0.f;
        }
        __syncthreads();
#pragma unroll
        for (int kk = 0; kk < KT; kk++) {
            float a[4], bb[4];
#pragma unroll
            for (int i = 0; i < 4; i++) a[i]  = Ws[kk][ty * 4 + i];
#pragma unroll
            for (int j = 0; j < 4; j++) bb[j] = Xs[kk][tx * 4 + j];
#pragma unroll
            for (int i = 0; i < 4; i++)
#pragma unroll
                for (int j = 0; j < 4; j++)
                    acc[i][j] += a[i] * bb[j];
        }
        __syncthreads();
    }

#pragma unroll
    for (int i = 0; i < 4; i++) {
        int o = o0 + ty * 4 + i;
        float scale = 1.f, shift = bias[o];
        if (gamma) {
            float inv = rsqrtf(var[o] + 1e-5f);
            scale = gamma[o] * inv;
            shift = (bias[o] - mean[o]) * scale + beta[o];
        }
#pragma unroll
        for (int j = 0; j < 4; j++) {
            int n = n0 + tx * 4 + j;
            if (n < Ndim) {
                float v = acc[i][j] * scale + shift;
                if (gamma) v = fmaxf(v, 0.f);
                Yb[(long)o * Ndim + n] = v;
            }
        }
    }
}

// ---------------------------------------------------------------------------
// QK logits: L[b,n,m] = sum_c Q[b,c,n] * K[b,c,m]   (both stored [C, N*])
// Cdim multiple of 16.
// ---------------------------------------------------------------------------
__global__ void qk_gemm(const float* __restrict__ Q, const float* __restrict__ Kt,
                        float* __restrict__ L, int Cdim, int Nq, int Nk)
{
    const int b = blockIdx.z;
    const float* Qb = Q  + (long)b * Cdim * Nq;
    const float* Kb = Kt + (long)b * Cdim * Nk;
    float* Lb = L + (long)b * Nq * Nk;

    __shared__ float Qs[KT][TILE];
    __shared__ float Ks[KT][TILE];

    const int t  = threadIdx.x;
    const int tx = t & 15;
    const int ty = t >> 4;
    const int m0 = blockIdx.x * TILE;   // key dim
    const int n0 = blockIdx.y * TILE;   // query dim

    float acc[4][4] = {};

    for (int k0 = 0; k0 < Cdim; k0 += KT) {
#pragma unroll
        for (int r = 0; r < 4; r++) {
            int idx = t + r * 256;
            int nn = idx % TILE;
            int kk = idx / TILE;
            int n = n0 + nn;
            Qs[kk][nn] = (n < Nq) ? Qb[(long)(k0 + kk) * Nq + n] : 0.f;
        }
#pragma unroll
        for (int r = 0; r < 4; r++) {
            int idx = t + r * 256;
            int mm = idx % TILE;
            int kk = idx / TILE;
            int m = m0 + mm;
            Ks[kk][mm] = (m < Nk) ? Kb[(long)(k0 + kk) * Nk + m] : 0.f;
        }
        __syncthreads();
#pragma unroll
        for (int kk = 0; kk < KT; kk++) {
            float a[4], bb[4];
#pragma unroll
            for (int i = 0; i < 4; i++) a[i]  = Qs[kk][ty * 4 + i];
#pragma unroll
            for (int j = 0; j < 4; j++) bb[j] = Ks[kk][tx * 4 + j];
#pragma unroll
            for (int i = 0; i < 4; i++)
#pragma unroll
                for (int j = 0; j < 4; j++)
                    acc[i][j] += a[i] * bb[j];
        }
        __syncthreads();
    }

#pragma unroll
    for (int i = 0; i < 4; i++) {
        int n = n0 + ty * 4 + i;
#pragma unroll
        for (int j = 0; j < 4; j++) {
            int m = m0 + tx * 4 + j;
            if (n < Nq && m < Nk) Lb[(long)n * Nk + m] = acc[i][j];
        }
    }
}

// ---------------------------------------------------------------------------
// Row softmax, row length M <= 1024, 256 threads, row held in registers.
// grid.x = B * Nq rows.
// ---------------------------------------------------------------------------
__global__ void softmax_rows(float* __restrict__ L, int M)
{
    size_t row = blockIdx.x;
    float* p = L + row * (size_t)M;
    const int t = threadIdx.x;

    float r[4];
    float mx = -1e30f;
#pragma unroll
    for (int i = 0; i < 4; i++) {
        int idx = t + i * 256;
        r[i] = (idx < M) ? p[idx] : -1e30f;
        mx = fmaxf(mx, r[i]);
    }
#pragma unroll
    for (int off = 16; off; off >>= 1)
        mx = fmaxf(mx, __shfl_xor_sync(0xffffffffu, mx, off));

    __shared__ float redmax[8];
    __shared__ float redsum[8];
    if ((t & 31) == 0) redmax[t >> 5] = mx;
    __syncthreads();
    mx = redmax[0];
#pragma unroll
    for (int w = 1; w < 8; w++) mx = fmaxf(mx, redmax[w]);

    float s = 0.f;
#pragma unroll
    for (int i = 0; i < 4; i++) {
        int idx = t + i * 256;
        r[i] = (idx < M) ? __expf(r[i] - mx) : 0.f;
        s += r[i];
    }
#pragma unroll
    for (int off = 16; off; off >>= 1)
        s += __shfl_xor_sync(0xffffffffu, s, off);
    if ((t & 31) == 0) redsum[t >> 5] = s;
    __syncthreads();
    s = 0.f;
#pragma unroll
    for (int w = 0; w < 8; w++) s += redsum[w];

    float inv = 1.f / s;
#pragma unroll
    for (int i = 0; i < 4; i++) {
        int idx = t + i * 256;
        if (idx < M) p[idx] = r[i] * inv;
    }
}

// ---------------------------------------------------------------------------
// PV: E[b,c,n] = sum_m G[b,c,m] * P[b,n,m]
// G stored [C, M] rows, P stored [Nq, M] rows. C multiple of 64.
// ---------------------------------------------------------------------------
__global__ void pv_gemm(const float* __restrict__ G, const float* __restrict__ P,
                        float* __restrict__ E,
                        int Nq, int M,
                        long g_bstride, long g_off,
                        long e_bstride, long e_off)
{
    const int b = blockIdx.z;
    const float* Gb = G + (long)b * g_bstride + g_off;  // [C, M]
    const float* Pb = P + (long)b * (long)Nq * M;       // [Nq, M]
    float* Eb = E + (long)b * e_bstride + e_off;        // [C, Nq]

    __shared__ float Gs[TILE][KT2 + 1];
    __shared__ float Ps[TILE][KT2 + 1];

    const int t  = threadIdx.x;
    const int tx = t & 15;
    const int ty = t >> 4;
    const int n0 = blockIdx.x * TILE;   // Nq
    const int c0 = blockIdx.y * TILE;   // C

    float acc[4][4] = {};

    for (int m0 = 0; m0 < M; m0 += KT2) {
#pragma unroll
        for (int r = 0; r < 8; r++) {
            int idx = t + r * 256;
            int mm = idx % KT2;
            int cc = idx / KT2;
            int m = m0 + mm;
            Gs[cc][mm] = (m < M) ? Gb[(long)(c0 + cc) * M + m] : 0.f;
        }
#pragma unroll
        for (int r = 0; r < 8; r++) {
            int idx = t + r * 256;
            int mm = idx % KT2;
            int nn = idx / KT2;
            int n = n0 + nn;
            int m = m0 + mm;
            Ps[nn][mm] = (n < Nq && m < M) ? Pb[(long)n * M + m] : 0.f;
        }
        __syncthreads();
#pragma unroll
        for (int kk = 0; kk < KT2; kk++) {
            float a[4], bb[4];
#pragma unroll
            for (int i = 0; i < 4; i++) a[i]  = Gs[ty * 4 + i][kk];
#pragma unroll
            for (int j = 0; j < 4; j++) bb[j] = Ps[tx * 4 + j][kk];
#pragma unroll
            for (int i = 0; i < 4; i++)
#pragma unroll
                for (int j = 0; j < 4; j++)
                    acc[i][j] += a[i] * bb[j];
        }
        __syncthreads();
    }

#pragma unroll
    for (int i = 0; i < 4; i++) {
        int c = c0 + ty * 4 + i;
#pragma unroll
        for (int j = 0; j < 4; j++) {
            int n = n0 + tx * 4 + j;
            if (n < Nq) Eb[(long)c * Nq + n] = acc[i][j];
        }
    }
}

// ---------------------------------------------------------------------------

extern "C" void kernel_launch(void* const* d_in, const int* in_sizes, int n_in,
                              void* d_out, int out_size)
{
    const float* zf  = (const float*)d_in[0];
    const float* xf  = (const float*)d_in[1];
    const float* Wq  = (const float*)d_in[2];
    const float* bq  = (const float*)d_in[3];
    const float* Ws_ = (const float*)d_in[4];
    const float* bs  = (const float*)d_in[5];
    const float* Wg  = (const float*)d_in[6];
    const float* bg  = (const float*)d_in[7];
    const float* g_gamma = (const float*)d_in[8];
    const float* g_beta  = (const float*)d_in[9];
    const float* g_mean  = (const float*)d_in[10];
    const float* g_var   = (const float*)d_in[11];
    const float* Wfi = (const float*)d_in[12];
    const float* bfi = (const float*)d_in[13];
    const float* fi_gamma = (const float*)d_in[14];
    const float* fi_beta  = (const float*)d_in[15];
    const float* fi_mean  = (const float*)d_in[16];
    const float* fi_var   = (const float*)d_in[17];
    float* out = (float*)d_out;

    float *XT, *CAT, *ZT, *ZG, *PS, *PZ;
    cudaGetSymbolAddress((void**)&XT,  g_XT);
    cudaGetSymbolAddress((void**)&CAT, g_CAT);
    cudaGetSymbolAddress((void**)&ZT,  g_ZT);
    cudaGetSymbolAddress((void**)&ZG,  g_ZG);
    cudaGetSymbolAddress((void**)&PS,  g_PS);
    cudaGetSymbolAddress((void**)&PZ,  g_PZ);

    const long CNX = (long)C_ * NX;
    const long CNZ = (long)C_ * NZ;

    dim3 blk(256);

    // 1) xf_trans = Wq @ xf + bq            -> XT [B,C,Nx]
    conv_gemm<<<dim3(16, 4, B_), blk>>>(Wq, xf, XT, bq,
                                        nullptr, nullptr, nullptr, nullptr,
                                        C_, NX, CNX, CNX, 0);
    // 2) xf_g = relu(bn(Wg @ xf + bg))      -> CAT slice [2C:3C]
    conv_gemm<<<dim3(16, 4, B_), blk>>>(Wg, xf, CAT, bg,
                                        g_gamma, g_beta, g_mean, g_var,
                                        C_, NX, CNX, 3 * CNX, 2 * CNX);
    // 3) zf_trans = Ws @ zf + bs            -> ZT [B,C,Nz]
    conv_gemm<<<dim3(1, 4, B_), blk>>>(Ws_, zf, ZT, bs,
                                       nullptr, nullptr, nullptr, nullptr,
                                       C_, NZ, CNZ, CNZ, 0);
    // 4) zf_g = relu(bn(Wg @ zf + bg))      -> ZG
    conv_gemm<<<dim3(1, 4, B_), blk>>>(Wg, zf, ZG, bg,
                                       g_gamma, g_beta, g_mean, g_var,
                                       C_, NZ, CNZ, CNZ, 0);
    // 5) self logits: PS[b,n,m] = XT.T @ XT
    qk_gemm<<<dim3(16, 16, B_), blk>>>(XT, XT, PS, C_, NX, NX);
    // 6) cross logits: PZ[b,n,m] = XT.T @ ZT
    qk_gemm<<<dim3(1, 16, B_), blk>>>(XT, ZT, PZ, C_, NX, NZ);
    // 7) softmax rows
    softmax_rows<<<dim3(B_ * NX), blk>>>(PS, NX);
    softmax_rows<<<dim3(B_ * NX), blk>>>(PZ, NZ);
    // 8) self_emb = xf_g @ PS^T             -> CAT slice [C:2C]
    pv_gemm<<<dim3(16, 4, B_), blk>>>(CAT, PS, CAT, NX, NX,
                                      3 * CNX, 2 * CNX, 3 * CNX, CNX);
    // 9) emb = zf_g @ PZ^T                  -> CAT slice [0:C]
    pv_gemm<<<dim3(16, 4, B_), blk>>>(ZG, PZ, CAT, NX, NZ,
                                      CNZ, 0, 3 * CNX, 0);
    // 10) out = relu(bn(Wfi @ CAT + bfi))
    conv_gemm<<<dim3(16, 4, B_), blk>>>(Wfi, CAT, out, bfi,
                                        fi_gamma, fi_beta, fi_mean, fi_var,
                                        3 * C_, NX, 3 * CNX, (long)O_ * NX, 0);
}

// round 3
// speedup vs baseline: 3.0186x; 3.0186x over previous
#include <cuda_runtime.h>
#include <cstdint>

// ---------------------------------------------------------------------------
// Problem constants
// ---------------------------------------------------------------------------
#define B_   32
#define C_   256
#define NX   961
#define NZ   49
#define PS_LD  976
#define PZ_LD  64
#define CAT_LD 976
#define ZG_LD  64

#define BM 128
#define BN 128
#define BK 32
#define SMS 36                       // padded smem row stride (words)
#define TILE_WORDS (128 * SMS)       // one matrix buffer
#define SMEM_BYTES (4 * TILE_WORDS * 4)   // A0,A1,B0,B1

// ---------------------------------------------------------------------------
// Scratch (device globals; no runtime allocation)
// ---------------------------------------------------------------------------
__device__ float g_XT [(size_t)B_ * NX * 256];        // xf_trans^T [B][Nx][C]
__device__ float g_ZT [(size_t)B_ * NZ * 256];        // zf_trans^T [B][Nz][C]
__device__ float g_ZG [(size_t)B_ * 256 * ZG_LD];     // zf_g       [B][C][64pad]
__device__ float g_CAT[(size_t)B_ * 768 * CAT_LD];    // [emb|self|xg] [B][3C][976pad]
__device__ float g_PS [(size_t)B_ * NX * PS_LD];      // self probs  [B][Nx][976pad]
__device__ float g_PZ [(size_t)B_ * NX * PZ_LD];      // cross probs [B][Nx][64pad]

// ---------------------------------------------------------------------------
__device__ __forceinline__ uint32_t cvt_tf32(float f) {
    uint32_t r;
    asm("cvt.rna.tf32.f32 %0, %1;" : "=r"(r) : "f"(f));
    return r;
}

__device__ __forceinline__ void mma_tf32(float* d, const uint32_t* a, const uint32_t* b) {
    asm volatile(
        "mma.sync.aligned.m16n8k8.row.col.f32.tf32.tf32.f32 "
        "{%0,%1,%2,%3}, {%4,%5,%6,%7}, {%8,%9}, {%0,%1,%2,%3};"
        : "+f"(d[0]), "+f"(d[1]), "+f"(d[2]), "+f"(d[3])
        : "r"(a[0]), "r"(a[1]), "r"(a[2]), "r"(a[3]), "r"(b[0]), "r"(b[1]));
}

// ---------------------------------------------------------------------------
// Tile loader -> smem [128 rows][32 k] padded stride SMS, converted to tf32.
// TRANS=false: src[row][k] (ld = row stride)
// TRANS=true : src[k][row] (transpose on load)
// 256 threads. Out-of-range elements zero-filled.
// ---------------------------------------------------------------------------
template<bool TRANS>
__device__ __forceinline__ void load_tile(uint32_t* sm, const float* __restrict__ src,
                                          int ld, int r0, int rmax, int k0, int kmax, int t)
{
    if (!TRANS) {
        if (((ld & 3) == 0) && (k0 + BK <= kmax)) {
#pragma unroll
            for (int i = 0; i < 4; i++) {
                int idx = i * 256 + t;
                int row = idx >> 3, c4 = idx & 7;
                float4 v = make_float4(0.f, 0.f, 0.f, 0.f);
                if (r0 + row < rmax)
                    v = *reinterpret_cast<const float4*>(src + (long)(r0 + row) * ld + k0 + c4 * 4);
                uint4 w;
                w.x = cvt_tf32(v.x); w.y = cvt_tf32(v.y);
                w.z = cvt_tf32(v.z); w.w = cvt_tf32(v.w);
                *reinterpret_cast<uint4*>(sm + row * SMS + c4 * 4) = w;
            }
        } else {
#pragma unroll
            for (int i = 0; i < 16; i++) {
                int idx = i * 256 + t;
                int row = idx >> 5, kk = idx & 31;
                float v = 0.f;
                if (r0 + row < rmax && k0 + kk < kmax)
                    v = src[(long)(r0 + row) * ld + k0 + kk];
                sm[row * SMS + kk] = cvt_tf32(v);
            }
        }
    } else {
#pragma unroll
        for (int i = 0; i < 16; i++) {
            int idx = i * 256 + t;
            int row = idx & 127, kk = idx >> 7;
            float v = 0.f;
            if (r0 + row < rmax && k0 + kk < kmax)
                v = src[(long)(k0 + kk) * ld + r0 + row];
            sm[row * SMS + kk] = cvt_tf32(v);
        }
    }
}

// ---------------------------------------------------------------------------
// tf32 mma.sync GEMM:  D[m][n] = epi( sum_k A[m][k] * B[n][k] )
// EPI 0: + bias[n]         EPI 1: relu(bn per row m)         EPI 2: plain
// 256 threads = 8 warps (4 x 2), warp tile 32x64, frags 2x8 of m16n8k8.
// ---------------------------------------------------------------------------
template<bool TA, bool TB, int EPI>
__global__ void __launch_bounds__(256, 2) mm(
    const float* __restrict__ A, const float* __restrict__ Bm, float* __restrict__ D,
    const float* __restrict__ bias, const float* __restrict__ gamma,
    const float* __restrict__ beta, const float* __restrict__ mean,
    const float* __restrict__ var,
    int M, int N, int K, int lda, int ldb, int ldd,
    long abs_, long bbs_, long dbs_)
{
    extern __shared__ uint32_t smem[];
    uint32_t* As = smem;                    // [2][TILE_WORDS]
    uint32_t* Bs = smem + 2 * TILE_WORDS;   // [2][TILE_WORDS]

    const int t = threadIdx.x;
    const int wid = t >> 5, lane = t & 31;
    const int warp_m = wid & 3, warp_n = wid >> 2;
    const int qid = lane >> 2, qtid = lane & 3;
    const int b = blockIdx.z;
    const int n0 = blockIdx.x * BN;
    const int m0 = blockIdx.y * BM;

    const float* Ab = A + (long)b * abs_;
    const float* Bb = Bm + (long)b * bbs_;
    float* Db = D + (long)b * dbs_;

    float acc[2][8][4];
#pragma unroll
    for (int i = 0; i < 2; i++)
#pragma unroll
        for (int j = 0; j < 8; j++)
#pragma unroll
            for (int k = 0; k < 4; k++) acc[i][j][k] = 0.f;

    const int T = (K + BK - 1) / BK;

    load_tile<TA>(As, Ab, lda, m0, M, 0, K, t);
    load_tile<TB>(Bs, Bb, ldb, n0, N, 0, K, t);
    __syncthreads();

    for (int tt = 0; tt < T; tt++) {
        const int cur = tt & 1;
        if (tt + 1 < T) {
            load_tile<TA>(As + (cur ^ 1) * TILE_WORDS, Ab, lda, m0, M, (tt + 1) * BK, K, t);
            load_tile<TB>(Bs + (cur ^ 1) * TILE_WORDS, Bb, ldb, n0, N, (tt + 1) * BK, K, t);
        }
        const uint32_t* Ac = As + cur * TILE_WORDS;
        const uint32_t* Bc = Bs + cur * TILE_WORDS;
#pragma unroll
        for (int ks = 0; ks < 4; ks++) {
            const int kk = ks * 8;
            uint32_t afr[2][4];
#pragma unroll
            for (int im = 0; im < 2; im++) {
                int base = (warp_m * 32 + im * 16 + qid) * SMS + kk + qtid;
                afr[im][0] = Ac[base];
                afr[im][1] = Ac[base + 8 * SMS];
                afr[im][2] = Ac[base + 4];
                afr[im][3] = Ac[base + 8 * SMS + 4];
            }
            uint32_t bfr[8][2];
#pragma unroll
            for (int jn = 0; jn < 8; jn++) {
                int base = (warp_n * 64 + jn * 8 + qid) * SMS + kk + qtid;
                bfr[jn][0] = Bc[base];
                bfr[jn][1] = Bc[base + 4];
            }
#pragma unroll
            for (int im = 0; im < 2; im++)
#pragma unroll
                for (int jn = 0; jn < 8; jn++)
                    mma_tf32(acc[im][jn], afr[im], bfr[jn]);
        }
        __syncthreads();
    }

    // ---- epilogue ----
    const int mb = m0 + warp_m * 32;
    const int nb = n0 + warp_n * 64;

    float scl[2][2], sft[2][2];
    if (EPI == 1) {
#pragma unroll
        for (int im = 0; im < 2; im++)
#pragma unroll
            for (int h = 0; h < 2; h++) {
                int r = mb + im * 16 + qid + h * 8;
                int ri = (r < M) ? r : 0;
                float inv = rsqrtf(var[ri] + 1e-5f);
                float s = gamma[ri] * inv;
                scl[im][h] = s;
                sft[im][h] = (bias[ri] - mean[ri]) * s + beta[ri];
            }
    }

#pragma unroll
    for (int im = 0; im < 2; im++) {
#pragma unroll
        for (int jn = 0; jn < 8; jn++) {
            int c0 = nb + jn * 8 + 2 * qtid;
#pragma unroll
            for (int h = 0; h < 2; h++) {
                int r = mb + im * 16 + qid + h * 8;
                if (r >= M) continue;
                float v0 = acc[im][jn][h * 2 + 0];
                float v1 = acc[im][jn][h * 2 + 1];
                if (EPI == 0) {
                    if (c0 < N)     v0 += bias[c0];
                    if (c0 + 1 < N) v1 += bias[c0 + 1];
                }
                if (EPI == 1) {
                    v0 = fmaxf(v0 * scl[im][h] + sft[im][h], 0.f);
                    v1 = fmaxf(v1 * scl[im][h] + sft[im][h], 0.f);
                }
                if (c0 < N)     Db[(long)r * ldd + c0]     = v0;
                if (c0 + 1 < N) Db[(long)r * ldd + c0 + 1] = v1;
            }
        }
    }
}

// ---------------------------------------------------------------------------
// Row softmax (row length M <= 1024, padded row stride ld)
// ---------------------------------------------------------------------------
__global__ void softmax_rows(float* __restrict__ L, int M, int ld)
{
    float* p = L + (size_t)blockIdx.x * ld;
    const int t = threadIdx.x;

    float r[4];
    float mx = -1e30f;
#pragma unroll
    for (int i = 0; i < 4; i++) {
        int idx = t + i * 256;
        r[i] = (idx < M) ? p[idx] : -1e30f;
        mx = fmaxf(mx, r[i]);
    }
#pragma unroll
    for (int off = 16; off; off >>= 1)
        mx = fmaxf(mx, __shfl_xor_sync(0xffffffffu, mx, off));

    __shared__ float redmax[8];
    __shared__ float redsum[8];
    if ((t & 31) == 0) redmax[t >> 5] = mx;
    __syncthreads();
    mx = redmax[0];
#pragma unroll
    for (int w = 1; w < 8; w++) mx = fmaxf(mx, redmax[w]);

    float s = 0.f;
#pragma unroll
    for (int i = 0; i < 4; i++) {
        int idx = t + i * 256;
        r[i] = (idx < M) ? __expf(r[i] - mx) : 0.f;
        s += r[i];
    }
#pragma unroll
    for (int off = 16; off; off >>= 1)
        s += __shfl_xor_sync(0xffffffffu, s, off);
    if ((t & 31) == 0) redsum[t >> 5] = s;
    __syncthreads();
    s = 0.f;
#pragma unroll
    for (int w = 0; w < 8; w++) s += redsum[w];

    float inv = 1.f / s;
#pragma unroll
    for (int i = 0; i < 4; i++) {
        int idx = t + i * 256;
        if (idx < M) p[idx] = r[i] * inv;
    }
}

// ---------------------------------------------------------------------------
extern "C" void kernel_launch(void* const* d_in, const int* in_sizes, int n_in,
                              void* d_out, int out_size)
{
    const float* zf  = (const float*)d_in[0];
    const float* xf  = (const float*)d_in[1];
    const float* Wq  = (const float*)d_in[2];
    const float* bq  = (const float*)d_in[3];
    const float* Ws_ = (const float*)d_in[4];
    const float* bs  = (const float*)d_in[5];
    const float* Wg  = (const float*)d_in[6];
    const float* bg  = (const float*)d_in[7];
    const float* g_gamma = (const float*)d_in[8];
    const float* g_beta  = (const float*)d_in[9];
    const float* g_mean  = (const float*)d_in[10];
    const float* g_var   = (const float*)d_in[11];
    const float* Wfi = (const float*)d_in[12];
    const float* bfi = (const float*)d_in[13];
    const float* fi_gamma = (const float*)d_in[14];
    const float* fi_beta  = (const float*)d_in[15];
    const float* fi_mean  = (const float*)d_in[16];
    const float* fi_var   = (const float*)d_in[17];
    float* out = (float*)d_out;

    float *XT, *ZT, *ZG, *CAT, *PS, *PZ;
    cudaGetSymbolAddress((void**)&XT,  g_XT);
    cudaGetSymbolAddress((void**)&ZT,  g_ZT);
    cudaGetSymbolAddress((void**)&ZG,  g_ZG);
    cudaGetSymbolAddress((void**)&CAT, g_CAT);
    cudaGetSymbolAddress((void**)&PS,  g_PS);
    cudaGetSymbolAddress((void**)&PZ,  g_PZ);

    static bool attr_done = false;
    if (!attr_done) {
        cudaFuncSetAttribute(mm<true,  false, 0>, cudaFuncAttributeMaxDynamicSharedMemorySize, SMEM_BYTES);
        cudaFuncSetAttribute(mm<false, true,  1>, cudaFuncAttributeMaxDynamicSharedMemorySize, SMEM_BYTES);
        cudaFuncSetAttribute(mm<false, false, 2>, cudaFuncAttributeMaxDynamicSharedMemorySize, SMEM_BYTES);
        attr_done = true;
    }

    const long CNX = (long)C_ * NX;
    const long CNZ = (long)C_ * NZ;
    const long XT_BS  = (long)NX * 256;
    const long ZT_BS  = (long)NZ * 256;
    const long ZG_BS  = (long)256 * ZG_LD;
    const long CAT_BS = (long)768 * CAT_LD;
    const long PS_BS  = (long)NX * PS_LD;
    const long PZ_BS  = (long)NX * PZ_LD;
    const long OUT_BS = (long)256 * NX;
    float* XG = CAT + (long)512 * CAT_LD;
    float* SE = CAT + (long)256 * CAT_LD;

    // 1) XT'[Nx,C] = xf^T @ Wq^T + bq
    mm<true, false, 0><<<dim3(2, 8, B_), 256, SMEM_BYTES>>>(
        xf, Wq, XT, bq, nullptr, nullptr, nullptr, nullptr,
        NX, 256, 256, NX, 256, 256, CNX, 0, XT_BS);
    // 2) ZT'[Nz,C] = zf^T @ Ws^T + bs
    mm<true, false, 0><<<dim3(2, 1, B_), 256, SMEM_BYTES>>>(
        zf, Ws_, ZT, bs, nullptr, nullptr, nullptr, nullptr,
        NZ, 256, 256, NZ, 256, 256, CNZ, 0, ZT_BS);
    // 3) XG[C,Nx] = relu(bn(Wg @ xf))
    mm<false, true, 1><<<dim3(8, 2, B_), 256, SMEM_BYTES>>>(
        Wg, xf, XG, bg, g_gamma, g_beta, g_mean, g_var,
        256, NX, 256, 256, NX, CAT_LD, 0, CNX, CAT_BS);
    // 4) ZG[C,Nz] = relu(bn(Wg @ zf))
    mm<false, true, 1><<<dim3(1, 2, B_), 256, SMEM_BYTES>>>(
        Wg, zf, ZG, bg, g_gamma, g_beta, g_mean, g_var,
        256, NZ, 256, 256, NZ, ZG_LD, 0, CNZ, ZG_BS);
    // 5) PS[Nx,Nx] = XT' @ XT'^T
    mm<false, false, 2><<<dim3(8, 8, B_), 256, SMEM_BYTES>>>(
        XT, XT, PS, nullptr, nullptr, nullptr, nullptr, nullptr,
        NX, NX, 256, 256, 256, PS_LD, XT_BS, XT_BS, PS_BS);
    // 6) PZ[Nx,Nz] = XT' @ ZT'^T
    mm<false, false, 2><<<dim3(1, 8, B_), 256, SMEM_BYTES>>>(
        XT, ZT, PZ, nullptr, nullptr, nullptr, nullptr, nullptr,
        NX, NZ, 256, 256, 256, PZ_LD, XT_BS, ZT_BS, PZ_BS);
    // 7) softmax
    softmax_rows<<<dim3(B_ * NX), 256>>>(PS, NX, PS_LD);
    softmax_rows<<<dim3(B_ * NX), 256>>>(PZ, NZ, PZ_LD);
    // 8) self_emb[C,Nx] = XG @ PS^T   (k = Nx positions)
    mm<false, false, 2><<<dim3(8, 2, B_), 256, SMEM_BYTES>>>(
        XG, PS, SE, nullptr, nullptr, nullptr, nullptr, nullptr,
        256, NX, NX, CAT_LD, PS_LD, CAT_LD, CAT_BS, PS_BS, CAT_BS);
    // 9) emb[C,Nx] = ZG @ PZ^T        (k = Nz positions)
    mm<false, false, 2><<<dim3(8, 2, B_), 256, SMEM_BYTES>>>(
        ZG, PZ, CAT, nullptr, nullptr, nullptr, nullptr, nullptr,
        256, NX, NZ, ZG_LD, PZ_LD, CAT_LD, ZG_BS, PZ_BS, CAT_BS);
    // 10) out[O,Nx] = relu(bn(Wfi @ CAT))
    mm<false, true, 1><<<dim3(8, 2, B_), 256, SMEM_BYTES>>>(
        Wfi, CAT, out, bfi, fi_gamma, fi_beta, fi_mean, fi_var,
        256, NX, 768, 768, CAT_LD, NX, 0, CAT_BS, OUT_BS);
}